// round 13
// baseline (speedup 1.0000x reference)
#include <cuda_runtime.h>
#include <cuda_fp16.h>
#include <cstdint>

// ---------------------------------------------------------------------------
// MessagePassing: out[q,:] += w_e * (ref[r_e,:] @ kernel[k_e,:,:])
// R13 (= R10 re-bench; three prior infra failures: 2x "device busy" at
// harness init + 1x GPUAcquisitionTimeout — pool capacity, zero kernel
// signal): B-column permutation (o = 16*(g>>1) + 2n + (g&1)) makes each
// thread's 16 output floats per row CONTIGUOUS in GMEM -> epilogue uses
// red.global.add.v4.f32 (8 per thread instead of 16 red.v2). Otherwise:
// TILE=128, 3 CTAs/SM, fp16 m16n8k16, fp16 ref mirror, cp.async pipeline.
// ---------------------------------------------------------------------------

#define D      64
#define TILE   128
#define MAXK   32
#define MAX_E  1703936
#define MAX_N  65536
#define GRID   444
#define MAXT   64

__device__ int g_hist[MAXK];
__device__ int g_cursor[MAXK];
__device__ int g_pstart[MAXK + 1];
__device__ int g_count[MAXK];
__device__ int g_tile_start[MAXK + 1];
__device__ int g_total_tiles;
__device__ int g_sorted[MAX_E];
__device__ uint32_t g_ref16[MAX_N * 32];   // fp16x2 mirror of ref_feat

// ---- SMEM layout ----------------------------------------------------------
#define SA_WORDS  36
#define SA_BYTES  (TILE * SA_WORDS * 4)    // 18432
#define OFF_A0    0u
#define OFF_A1    18432u
#define OFF_B     36864u                   // 4 steps x 32 lanes x 20 words
#define OFF_Q     47104u                   // 2 x 128 ints
#define OFF_W     48128u                   // 2 x 128 floats
#define OFF_MK    49152u
#define OFF_MB    49408u
#define OFF_MN    49664u
#define OFF_TS    49920u                   // 33 ints (pad 144)
#define OFF_PS    50064u
#define OFF_CN    50208u
#define DYN_SMEM  50432

__device__ __forceinline__ uint32_t smem_u32(const void* p) {
    uint32_t a;
    asm("{ .reg .u64 t; cvta.to.shared.u64 t, %1; cvt.u32.u64 %0, t; }"
        : "=r"(a) : "l"(p));
    return a;
}
__device__ __forceinline__ uint32_t pack_h2(float lo, float hi) {
    __half2 h = __floats2half2_rn(lo, hi);
    return *(uint32_t*)&h;
}
__device__ __forceinline__ void cp16(uint32_t dst, const void* src, int sz) {
    asm volatile("cp.async.cg.shared.global [%0], [%1], 16, %2;"
                 :: "r"(dst), "l"(src), "r"(sz) : "memory");
}
#define CP_COMMIT() asm volatile("cp.async.commit_group;" ::: "memory")
#define CP_WAIT0()  asm volatile("cp.async.wait_group 0;" ::: "memory")

__device__ __forceinline__ void red_v4(float* p, float a, float b,
                                       float c, float d) {
    asm volatile("red.global.add.v4.f32 [%0], {%1, %2, %3, %4};"
                 :: "l"(p), "f"(a), "f"(b), "f"(c), "f"(d) : "memory");
}

__device__ __forceinline__ void mma_f16(float& c0, float& c1, float& c2, float& c3,
                                        uint32_t a0, uint32_t a1, uint32_t a2,
                                        uint32_t a3, uint32_t b0, uint32_t b1) {
    asm volatile(
        "mma.sync.aligned.m16n8k16.row.col.f32.f16.f16.f32 "
        "{%0,%1,%2,%3}, {%4,%5,%6,%7}, {%8,%9}, {%0,%1,%2,%3};"
        : "+f"(c0), "+f"(c1), "+f"(c2), "+f"(c3)
        : "r"(a0), "r"(a1), "r"(a2), "r"(a3), "r"(b0), "r"(b1));
}

// ---- prep: fp16 mirror of ref_feat + histogram zero -----------------------
__global__ void ref16_kernel(const float* __restrict__ ref, int nwords) {
    int i = blockIdx.x * blockDim.x + threadIdx.x;
    if (blockIdx.x == 0 && threadIdx.x < MAXK) g_hist[threadIdx.x] = 0;
    if (i < nwords) {
        float2 v = ((const float2*)ref)[i];
        g_ref16[i] = pack_h2(v.x, v.y);
    }
}

// ---- sort passes ----------------------------------------------------------
__global__ void hist_kernel(const int* __restrict__ ek, int E) {
    __shared__ int sh[MAXK];
    if (threadIdx.x < MAXK) sh[threadIdx.x] = 0;
    __syncthreads();
    for (int i = blockIdx.x * blockDim.x + threadIdx.x; i < E;
         i += gridDim.x * blockDim.x)
        atomicAdd(&sh[ek[i]], 1);
    __syncthreads();
    if (threadIdx.x < MAXK) {
        int v = sh[threadIdx.x];
        if (v) atomicAdd(&g_hist[threadIdx.x], v);
    }
}

// warp-parallel exclusive scan over 27 buckets
__global__ void scan_kernel(int K0) {
    int lane = threadIdx.x;
    int c = (lane < K0) ? g_hist[lane] : 0;
    int nt = (c + TILE - 1) / TILE;
    int p = nt * TILE, t = nt;
    int ip = p, it = t;
    #pragma unroll
    for (int off = 1; off < 32; off <<= 1) {
        int vp = __shfl_up_sync(0xFFFFFFFFu, ip, off);
        int vt = __shfl_up_sync(0xFFFFFFFFu, it, off);
        if (lane >= off) { ip += vp; it += vt; }
    }
    int ep = ip - p, et = it - t;
    int totT = __shfl_sync(0xFFFFFFFFu, it, 31);
    if (lane < K0) {
        g_pstart[lane] = ep;
        g_cursor[lane] = ep;
        g_count[lane]  = c;
        g_tile_start[lane] = et;
    } else {
        g_tile_start[lane] = totT;
    }
    if (lane == 31) {
        g_tile_start[32] = totT;
        g_total_tiles = totT;
    }
}

__global__ void scatter_kernel(const int* __restrict__ ek, int E) {
    __shared__ int sc[MAXK], sb[MAXK];
    int chunk = (E + gridDim.x - 1) / gridDim.x;
    int lo = blockIdx.x * chunk;
    int hi = min(lo + chunk, E);
    if (threadIdx.x < MAXK) sc[threadIdx.x] = 0;
    __syncthreads();
    for (int i = lo + threadIdx.x; i < hi; i += blockDim.x)
        atomicAdd(&sc[ek[i]], 1);
    __syncthreads();
    if (threadIdx.x < MAXK) {
        int c = sc[threadIdx.x];
        sb[threadIdx.x] = c ? atomicAdd(&g_cursor[threadIdx.x], c) : 0;
        sc[threadIdx.x] = 0;
    }
    __syncthreads();
    for (int i = lo + threadIdx.x; i < hi; i += blockDim.x) {
        int k = ek[i];
        int pos = sb[k] + atomicAdd(&sc[k], 1);
        g_sorted[pos] = i;
    }
}

// ---- main fused MMA kernel ------------------------------------------------
__global__ __launch_bounds__(256, 3) void mp_mma(
    const float* __restrict__ kernelW,
    const int*   __restrict__ e_ref,
    const int*   __restrict__ e_query,
    const float* __restrict__ e_weight,
    float*       __restrict__ out)
{
    extern __shared__ char sm[];
    uint32_t sa0 = smem_u32(sm + OFF_A0);
    uint32_t sa1 = smem_u32(sm + OFF_A1);
    uint32_t*    s_Bw = (uint32_t*)(sm + OFF_B);
    const uint4* s_B4 = (const uint4*)(sm + OFF_B);
    int   (*s_q)[TILE] = (int (*)[TILE])(sm + OFF_Q);
    float (*s_w)[TILE] = (float (*)[TILE])(sm + OFF_W);
    int* s_mk = (int*)(sm + OFF_MK);
    int* s_mb = (int*)(sm + OFF_MB);
    int* s_mn = (int*)(sm + OFF_MN);
    int* s_ts = (int*)(sm + OFF_TS);
    int* s_ps = (int*)(sm + OFF_PS);
    int* s_cn = (int*)(sm + OFF_CN);

    int tid = threadIdx.x, wid = tid >> 5, lane = tid & 31;
    int g = lane >> 2, t4 = lane & 3;

    if (tid < MAXK + 1) s_ts[tid] = g_tile_start[tid];
    else if (tid >= 64 && tid < 64 + MAXK) s_ps[tid - 64] = g_pstart[tid - 64];
    else if (tid >= 128 && tid < 128 + MAXK) s_cn[tid - 128] = g_count[tid - 128];
    __syncthreads();

    int total = g_total_tiles;
    int per = (total + GRID - 1) / GRID;
    int t0 = blockIdx.x * per;
    int t1 = min(t0 + per, total);
    int ntiles = min(t1 - t0, MAXT);
    if (ntiles <= 0) return;

    for (int j = tid; j < ntiles; j += 256) {
        int tile = t0 + j;
        int kk = 0;
        while (tile >= s_ts[kk + 1]) kk++;
        int local = tile - s_ts[kk];
        s_mk[j] = kk;
        s_mb[j] = s_ps[kk] + local * TILE;
        int n = s_cn[kk] - local * TILE;
        s_mn[j] = n > TILE ? TILE : n;
    }
    __syncthreads();

    int row = tid >> 1, half = tid & 1;
    uint32_t dst_off = (uint32_t)row * (SA_WORDS * 4) + (uint32_t)half * 64u;

    // ---- prologue: gather tile 0 ------------------------------------------
    {
        int n0 = s_mn[0], base = s_mb[0];
        int r = -1, q = -1;
        float w = 0.f;
        if (row < n0) {
            int e = g_sorted[base + row];
            r = e_ref[e];
            q = e_query[e];
            w = e_weight[e];
        }
        if (half == 0) { s_q[0][row] = q; s_w[0][row] = w; }
        const char* src =
            (const char*)(g_ref16 + (size_t)(r < 0 ? 0 : r) * 32) + half * 64;
        int sz = (r < 0) ? 0 : 16;
        uint32_t d0 = sa0 + dst_off;
        #pragma unroll
        for (int j = 0; j < 4; ++j) cp16(d0 + j * 16, src + j * 16, sz);
        CP_COMMIT();
    }

    int r_nx = -1, q_nx = -1;
    float w_nx = 0.f;
    if (ntiles > 1) {
        int n1 = s_mn[1], base = s_mb[1];
        if (row < n1) {
            int e = g_sorted[base + row];
            r_nx = e_ref[e];
            q_nx = e_query[e];
            w_nx = e_weight[e];
        }
    }

    int prevk = -1;
    for (int ii = 0; ii < ntiles; ++ii) {
        int buf = ii & 1;
        uint32_t sb_addr = buf ? sa0 : sa1;
        int k = s_mk[ii];

        CP_WAIT0();
        __syncthreads();

        // rebuild fragment-major fp16 B on kernel change (block-uniform).
        // Column permutation: MMA-col slot (n, g) holds GMEM output channel
        //   o = 16*(g>>1) + 2n + (g&1)
        // so consumer thread (g',t4') rows own GMEM cols [16*t4', 16*t4'+16).
        if (k != prevk) {
            if (wid < 4) {
                const float* kw = kernelW + (size_t)k * D * D;
                int s = wid;
                uint32_t* bp = s_Bw + (s * 32 + lane) * 20;
                int d0 = s * 16 + 2 * t4;
                int obase = 16 * (g >> 1) + (g & 1);
                #pragma unroll
                for (int n = 0; n < 8; ++n) {
                    int o = obase + 2 * n;
                    bp[2 * n]     = pack_h2(kw[d0 * D + o],       kw[(d0 + 1) * D + o]);
                    bp[2 * n + 1] = pack_h2(kw[(d0 + 8) * D + o], kw[(d0 + 9) * D + o]);
                }
            }
            prevk = k;
            __syncthreads();
        }

        // issue gather for tile ii+1
        if (ii + 1 < ntiles) {
            if (half == 0) { s_q[buf ^ 1][row] = q_nx; s_w[buf ^ 1][row] = w_nx; }
            const char* src =
                (const char*)(g_ref16 + (size_t)(r_nx < 0 ? 0 : r_nx) * 32) + half * 64;
            int sz = (r_nx < 0) ? 0 : 16;
            uint32_t d1 = sb_addr + dst_off;
            #pragma unroll
            for (int j = 0; j < 4; ++j) cp16(d1 + j * 16, src + j * 16, sz);
        }
        CP_COMMIT();

        // prefetch indices for tile ii+2
        r_nx = -1; q_nx = -1; w_nx = 0.f;
        if (ii + 2 < ntiles) {
            int nn = s_mn[ii + 2], base = s_mb[ii + 2];
            if (row < nn) {
                int e = g_sorted[base + row];
                r_nx = e_ref[e];
                q_nx = e_query[e];
                w_nx = e_weight[e];
            }
        }

        // ---- MMA: warp owns rows [16w, 16w+16), 4 k16-steps ---------------
        float acc[8][4];
        #pragma unroll
        for (int i = 0; i < 8; ++i)
            #pragma unroll
            for (int j = 0; j < 4; ++j) acc[i][j] = 0.f;

        {
            const uint32_t* A =
                (const uint32_t*)(sm + (buf ? OFF_A1 : OFF_A0));
            const uint32_t* A0 = A + (wid * 16 + g) * SA_WORDS;
            const uint32_t* A1 = A0 + 8 * SA_WORDS;
            #pragma unroll
            for (int s = 0; s < 4; ++s) {
                uint32_t a0 = A0[s * 8 + t4];
                uint32_t a1 = A1[s * 8 + t4];
                uint32_t a2 = A0[s * 8 + t4 + 4];
                uint32_t a3 = A1[s * 8 + t4 + 4];
                const uint4* bp = s_B4 + (s * 160 + lane * 5);
                #pragma unroll
                for (int m = 0; m < 4; ++m) {
                    uint4 bb = bp[m];
                    mma_f16(acc[2 * m][0], acc[2 * m][1], acc[2 * m][2],
                            acc[2 * m][3], a0, a1, a2, a3, bb.x, bb.y);
                    mma_f16(acc[2 * m + 1][0], acc[2 * m + 1][1],
                            acc[2 * m + 1][2], acc[2 * m + 1][3],
                            a0, a1, a2, a3, bb.z, bb.w);
                }
            }
        }

        // ---- epilogue: weight-scale + contiguous red.v4 atomics -----------
        // acc[n][0|1] -> gmem col 16*t4 + 2n (+1)  (row r0)
        // acc[n][2|3] -> same cols, row r1
        {
            int r0 = wid * 16 + g, r1 = r0 + 8;
            int q0 = s_q[buf][r0], q1 = s_q[buf][r1];
            float w0 = s_w[buf][r0], w1 = s_w[buf][r1];
            if (q0 >= 0) {
                float* p0 = out + (size_t)q0 * D + 16 * t4;
                #pragma unroll
                for (int j = 0; j < 4; ++j)
                    red_v4(p0 + 4 * j,
                           acc[2 * j][0] * w0, acc[2 * j][1] * w0,
                           acc[2 * j + 1][0] * w0, acc[2 * j + 1][1] * w0);
            }
            if (q1 >= 0) {
                float* p1 = out + (size_t)q1 * D + 16 * t4;
                #pragma unroll
                for (int j = 0; j < 4; ++j)
                    red_v4(p1 + 4 * j,
                           acc[2 * j][2] * w1, acc[2 * j][3] * w1,
                           acc[2 * j + 1][2] * w1, acc[2 * j + 1][3] * w1);
            }
        }
    }
}

// ---------------------------------------------------------------------------
extern "C" void kernel_launch(void* const* d_in, const int* in_sizes, int n_in,
                              void* d_out, int out_size) {
    const float* kernelW  = (const float*)d_in[0];
    const float* ref      = (const float*)d_in[1];
    const int*   e_kernel = (const int*)d_in[2];
    const int*   e_ref    = (const int*)d_in[3];
    const int*   e_query  = (const int*)d_in[4];
    const float* e_weight =
        (n_in >= 7) ? (const float*)d_in[6] : (const float*)d_in[5];

    int E  = in_sizes[2];
    int K0 = in_sizes[0] / (D * D);
    int N  = in_sizes[1] / D;
    int nwords = N * 32;

    cudaMemsetAsync(d_out, 0, (size_t)out_size * sizeof(float), 0);

    ref16_kernel<<<(nwords + 255) / 256, 256>>>(ref, nwords);
    hist_kernel<<<256, 256>>>(e_kernel, E);
    scan_kernel<<<1, 32>>>(K0);
    scatter_kernel<<<592, 256>>>(e_kernel, E);

    cudaFuncSetAttribute(mp_mma, cudaFuncAttributeMaxDynamicSharedMemorySize,
                         DYN_SMEM);
    mp_mma<<<GRID, 256, DYN_SMEM>>>(kernelW, e_ref, e_query, e_weight,
                                    (float*)d_out);
}

// round 17
// speedup vs baseline: 1.0337x; 1.0337x over previous
#include <cuda_runtime.h>
#include <cuda_fp16.h>
#include <cstdint>

// ---------------------------------------------------------------------------
// MessagePassing: out[q,:] += w_e * (ref[r_e,:] @ kernel[k_e,:,:])
// R17 (= R14 re-bench; 4th attempt — four GPUAcquisitionTimeouts carried
// zero kernel signal): prep reorganization. ref16 fused into scatter (extra
// blocks), hist self-zeroed by scan (stateless across graph replays).
// Kernel order: hist(0), scan(1), scatfuse(2), mp_mma(3) -> ncu capture
// slot (#3) lands on mp_mma. Main kernel unchanged from R13 (TILE=128,
// 3 CTAs/SM, fp16 m16n8k16, B-column permutation + red.add.v4 epilogue).
// ---------------------------------------------------------------------------

#define D      64
#define TILE   128
#define MAXK   32
#define MAX_E  1703936
#define MAX_N  65536
#define GRID   444
#define MAXT   64
#define SCAT_BLOCKS 592

__device__ int g_hist[MAXK];           // static-zeroed; scan re-zeroes per call
__device__ int g_cursor[MAXK];
__device__ int g_pstart[MAXK + 1];
__device__ int g_count[MAXK];
__device__ int g_tile_start[MAXK + 1];
__device__ int g_total_tiles;
__device__ int g_sorted[MAX_E];
__device__ uint32_t g_ref16[MAX_N * 32];   // fp16x2 mirror of ref_feat

// ---- SMEM layout ----------------------------------------------------------
#define SA_WORDS  36
#define SA_BYTES  (TILE * SA_WORDS * 4)    // 18432
#define OFF_A0    0u
#define OFF_A1    18432u
#define OFF_B     36864u                   // 4 steps x 32 lanes x 20 words
#define OFF_Q     47104u                   // 2 x 128 ints
#define OFF_W     48128u                   // 2 x 128 floats
#define OFF_MK    49152u
#define OFF_MB    49408u
#define OFF_MN    49664u
#define OFF_TS    49920u                   // 33 ints (pad 144)
#define OFF_PS    50064u
#define OFF_CN    50208u
#define DYN_SMEM  50432

__device__ __forceinline__ uint32_t smem_u32(const void* p) {
    uint32_t a;
    asm("{ .reg .u64 t; cvta.to.shared.u64 t, %1; cvt.u32.u64 %0, t; }"
        : "=r"(a) : "l"(p));
    return a;
}
__device__ __forceinline__ uint32_t pack_h2(float lo, float hi) {
    __half2 h = __floats2half2_rn(lo, hi);
    return *(uint32_t*)&h;
}
__device__ __forceinline__ void cp16(uint32_t dst, const void* src, int sz) {
    asm volatile("cp.async.cg.shared.global [%0], [%1], 16, %2;"
                 :: "r"(dst), "l"(src), "r"(sz) : "memory");
}
#define CP_COMMIT() asm volatile("cp.async.commit_group;" ::: "memory")
#define CP_WAIT0()  asm volatile("cp.async.wait_group 0;" ::: "memory")

__device__ __forceinline__ void red_v4(float* p, float a, float b,
                                       float c, float d) {
    asm volatile("red.global.add.v4.f32 [%0], {%1, %2, %3, %4};"
                 :: "l"(p), "f"(a), "f"(b), "f"(c), "f"(d) : "memory");
}

__device__ __forceinline__ void mma_f16(float& c0, float& c1, float& c2, float& c3,
                                        uint32_t a0, uint32_t a1, uint32_t a2,
                                        uint32_t a3, uint32_t b0, uint32_t b1) {
    asm volatile(
        "mma.sync.aligned.m16n8k16.row.col.f32.f16.f16.f32 "
        "{%0,%1,%2,%3}, {%4,%5,%6,%7}, {%8,%9}, {%0,%1,%2,%3};"
        : "+f"(c0), "+f"(c1), "+f"(c2), "+f"(c3)
        : "r"(a0), "r"(a1), "r"(a2), "r"(a3), "r"(b0), "r"(b1));
}

// ---- kernel 0: histogram (g_hist zeroed by previous call's scan) ----------
__global__ void hist_kernel(const int* __restrict__ ek, int E) {
    __shared__ int sh[MAXK];
    if (threadIdx.x < MAXK) sh[threadIdx.x] = 0;
    __syncthreads();
    for (int i = blockIdx.x * blockDim.x + threadIdx.x; i < E;
         i += gridDim.x * blockDim.x)
        atomicAdd(&sh[ek[i]], 1);
    __syncthreads();
    if (threadIdx.x < MAXK) {
        int v = sh[threadIdx.x];
        if (v) atomicAdd(&g_hist[threadIdx.x], v);
    }
}

// ---- kernel 1: warp-parallel scan; re-zeroes g_hist for next call ---------
__global__ void scan_kernel(int K0) {
    int lane = threadIdx.x;
    int c = (lane < K0) ? g_hist[lane] : 0;
    if (lane < MAXK) g_hist[lane] = 0;   // leave zeroed for next graph replay
    int nt = (c + TILE - 1) / TILE;
    int p = nt * TILE, t = nt;
    int ip = p, it = t;
    #pragma unroll
    for (int off = 1; off < 32; off <<= 1) {
        int vp = __shfl_up_sync(0xFFFFFFFFu, ip, off);
        int vt = __shfl_up_sync(0xFFFFFFFFu, it, off);
        if (lane >= off) { ip += vp; it += vt; }
    }
    int ep = ip - p, et = it - t;
    int totT = __shfl_sync(0xFFFFFFFFu, it, 31);
    if (lane < K0) {
        g_pstart[lane] = ep;
        g_cursor[lane] = ep;
        g_count[lane]  = c;
        g_tile_start[lane] = et;
    } else {
        g_tile_start[lane] = totT;
    }
    if (lane == 31) {
        g_tile_start[32] = totT;
        g_total_tiles = totT;
    }
}

// ---- kernel 2: fused edge scatter (blocks < SCAT_BLOCKS) + fp16 mirror ----
__global__ void scatfuse_kernel(const int* __restrict__ ek, int E,
                                const float* __restrict__ ref, int nvec) {
    if (blockIdx.x < SCAT_BLOCKS) {
        __shared__ int sc[MAXK], sb[MAXK];
        int chunk = (E + SCAT_BLOCKS - 1) / SCAT_BLOCKS;
        int lo = blockIdx.x * chunk;
        int hi = min(lo + chunk, E);
        if (threadIdx.x < MAXK) sc[threadIdx.x] = 0;
        __syncthreads();
        for (int i = lo + threadIdx.x; i < hi; i += blockDim.x)
            atomicAdd(&sc[ek[i]], 1);
        __syncthreads();
        if (threadIdx.x < MAXK) {
            int c = sc[threadIdx.x];
            sb[threadIdx.x] = c ? atomicAdd(&g_cursor[threadIdx.x], c) : 0;
            sc[threadIdx.x] = 0;
        }
        __syncthreads();
        for (int i = lo + threadIdx.x; i < hi; i += blockDim.x) {
            int k = ek[i];
            int pos = sb[k] + atomicAdd(&sc[k], 1);
            g_sorted[pos] = i;
        }
    } else {
        // fp16 mirror: thread handles one float4 -> uint2 (2 fp16x2 words)
        int i = (blockIdx.x - SCAT_BLOCKS) * blockDim.x + threadIdx.x;
        if (i < nvec) {
            float4 v = ((const float4*)ref)[i];
            uint2 u;
            u.x = pack_h2(v.x, v.y);
            u.y = pack_h2(v.z, v.w);
            ((uint2*)g_ref16)[i] = u;
        }
    }
}

// ---- kernel 3: main fused MMA kernel (ncu capture slot) -------------------
__global__ __launch_bounds__(256, 3) void mp_mma(
    const float* __restrict__ kernelW,
    const int*   __restrict__ e_ref,
    const int*   __restrict__ e_query,
    const float* __restrict__ e_weight,
    float*       __restrict__ out)
{
    extern __shared__ char sm[];
    uint32_t sa0 = smem_u32(sm + OFF_A0);
    uint32_t sa1 = smem_u32(sm + OFF_A1);
    uint32_t*    s_Bw = (uint32_t*)(sm + OFF_B);
    const uint4* s_B4 = (const uint4*)(sm + OFF_B);
    int   (*s_q)[TILE] = (int (*)[TILE])(sm + OFF_Q);
    float (*s_w)[TILE] = (float (*)[TILE])(sm + OFF_W);
    int* s_mk = (int*)(sm + OFF_MK);
    int* s_mb = (int*)(sm + OFF_MB);
    int* s_mn = (int*)(sm + OFF_MN);
    int* s_ts = (int*)(sm + OFF_TS);
    int* s_ps = (int*)(sm + OFF_PS);
    int* s_cn = (int*)(sm + OFF_CN);

    int tid = threadIdx.x, wid = tid >> 5, lane = tid & 31;
    int g = lane >> 2, t4 = lane & 3;

    if (tid < MAXK + 1) s_ts[tid] = g_tile_start[tid];
    else if (tid >= 64 && tid < 64 + MAXK) s_ps[tid - 64] = g_pstart[tid - 64];
    else if (tid >= 128 && tid < 128 + MAXK) s_cn[tid - 128] = g_count[tid - 128];
    __syncthreads();

    int total = g_total_tiles;
    int per = (total + GRID - 1) / GRID;
    int t0 = blockIdx.x * per;
    int t1 = min(t0 + per, total);
    int ntiles = min(t1 - t0, MAXT);
    if (ntiles <= 0) return;

    for (int j = tid; j < ntiles; j += 256) {
        int tile = t0 + j;
        int kk = 0;
        while (tile >= s_ts[kk + 1]) kk++;
        int local = tile - s_ts[kk];
        s_mk[j] = kk;
        s_mb[j] = s_ps[kk] + local * TILE;
        int n = s_cn[kk] - local * TILE;
        s_mn[j] = n > TILE ? TILE : n;
    }
    __syncthreads();

    int row = tid >> 1, half = tid & 1;
    uint32_t dst_off = (uint32_t)row * (SA_WORDS * 4) + (uint32_t)half * 64u;

    // ---- prologue: gather tile 0 ------------------------------------------
    {
        int n0 = s_mn[0], base = s_mb[0];
        int r = -1, q = -1;
        float w = 0.f;
        if (row < n0) {
            int e = g_sorted[base + row];
            r = e_ref[e];
            q = e_query[e];
            w = e_weight[e];
        }
        if (half == 0) { s_q[0][row] = q; s_w[0][row] = w; }
        const char* src =
            (const char*)(g_ref16 + (size_t)(r < 0 ? 0 : r) * 32) + half * 64;
        int sz = (r < 0) ? 0 : 16;
        uint32_t d0 = sa0 + dst_off;
        #pragma unroll
        for (int j = 0; j < 4; ++j) cp16(d0 + j * 16, src + j * 16, sz);
        CP_COMMIT();
    }

    int r_nx = -1, q_nx = -1;
    float w_nx = 0.f;
    if (ntiles > 1) {
        int n1 = s_mn[1], base = s_mb[1];
        if (row < n1) {
            int e = g_sorted[base + row];
            r_nx = e_ref[e];
            q_nx = e_query[e];
            w_nx = e_weight[e];
        }
    }

    int prevk = -1;
    for (int ii = 0; ii < ntiles; ++ii) {
        int buf = ii & 1;
        uint32_t sb_addr = buf ? sa0 : sa1;
        int k = s_mk[ii];

        CP_WAIT0();
        __syncthreads();

        // rebuild fragment-major fp16 B on kernel change (block-uniform).
        // Column permutation: MMA-col slot (n, g) holds GMEM output channel
        //   o = 16*(g>>1) + 2n + (g&1)
        // so consumer thread (g',t4') rows own GMEM cols [16*t4', 16*t4'+16).
        if (k != prevk) {
            if (wid < 4) {
                const float* kw = kernelW + (size_t)k * D * D;
                int s = wid;
                uint32_t* bp = s_Bw + (s * 32 + lane) * 20;
                int d0 = s * 16 + 2 * t4;
                int obase = 16 * (g >> 1) + (g & 1);
                #pragma unroll
                for (int n = 0; n < 8; ++n) {
                    int o = obase + 2 * n;
                    bp[2 * n]     = pack_h2(kw[d0 * D + o],       kw[(d0 + 1) * D + o]);
                    bp[2 * n + 1] = pack_h2(kw[(d0 + 8) * D + o], kw[(d0 + 9) * D + o]);
                }
            }
            prevk = k;
            __syncthreads();
        }

        // issue gather for tile ii+1
        if (ii + 1 < ntiles) {
            if (half == 0) { s_q[buf ^ 1][row] = q_nx; s_w[buf ^ 1][row] = w_nx; }
            const char* src =
                (const char*)(g_ref16 + (size_t)(r_nx < 0 ? 0 : r_nx) * 32) + half * 64;
            int sz = (r_nx < 0) ? 0 : 16;
            uint32_t d1 = sb_addr + dst_off;
            #pragma unroll
            for (int j = 0; j < 4; ++j) cp16(d1 + j * 16, src + j * 16, sz);
        }
        CP_COMMIT();

        // prefetch indices for tile ii+2
        r_nx = -1; q_nx = -1; w_nx = 0.f;
        if (ii + 2 < ntiles) {
            int nn = s_mn[ii + 2], base = s_mb[ii + 2];
            if (row < nn) {
                int e = g_sorted[base + row];
                r_nx = e_ref[e];
                q_nx = e_query[e];
                w_nx = e_weight[e];
            }
        }

        // ---- MMA: warp owns rows [16w, 16w+16), 4 k16-steps ---------------
        float acc[8][4];
        #pragma unroll
        for (int i = 0; i < 8; ++i)
            #pragma unroll
            for (int j = 0; j < 4; ++j) acc[i][j] = 0.f;

        {
            const uint32_t* A =
                (const uint32_t*)(sm + (buf ? OFF_A1 : OFF_A0));
            const uint32_t* A0 = A + (wid * 16 + g) * SA_WORDS;
            const uint32_t* A1 = A0 + 8 * SA_WORDS;
            #pragma unroll
            for (int s = 0; s < 4; ++s) {
                uint32_t a0 = A0[s * 8 + t4];
                uint32_t a1 = A1[s * 8 + t4];
                uint32_t a2 = A0[s * 8 + t4 + 4];
                uint32_t a3 = A1[s * 8 + t4 + 4];
                const uint4* bp = s_B4 + (s * 160 + lane * 5);
                #pragma unroll
                for (int m = 0; m < 4; ++m) {
                    uint4 bb = bp[m];
                    mma_f16(acc[2 * m][0], acc[2 * m][1], acc[2 * m][2],
                            acc[2 * m][3], a0, a1, a2, a3, bb.x, bb.y);
                    mma_f16(acc[2 * m + 1][0], acc[2 * m + 1][1],
                            acc[2 * m + 1][2], acc[2 * m + 1][3],
                            a0, a1, a2, a3, bb.z, bb.w);
                }
            }
        }

        // ---- epilogue: weight-scale + contiguous red.v4 atomics -----------
        {
            int r0 = wid * 16 + g, r1 = r0 + 8;
            int q0 = s_q[buf][r0], q1 = s_q[buf][r1];
            float w0 = s_w[buf][r0], w1 = s_w[buf][r1];
            if (q0 >= 0) {
                float* p0 = out + (size_t)q0 * D + 16 * t4;
                #pragma unroll
                for (int j = 0; j < 4; ++j)
                    red_v4(p0 + 4 * j,
                           acc[2 * j][0] * w0, acc[2 * j][1] * w0,
                           acc[2 * j + 1][0] * w0, acc[2 * j + 1][1] * w0);
            }
            if (q1 >= 0) {
                float* p1 = out + (size_t)q1 * D + 16 * t4;
                #pragma unroll
                for (int j = 0; j < 4; ++j)
                    red_v4(p1 + 4 * j,
                           acc[2 * j][2] * w1, acc[2 * j][3] * w1,
                           acc[2 * j + 1][2] * w1, acc[2 * j + 1][3] * w1);
            }
        }
    }
}

// ---------------------------------------------------------------------------
extern "C" void kernel_launch(void* const* d_in, const int* in_sizes, int n_in,
                              void* d_out, int out_size) {
    const float* kernelW  = (const float*)d_in[0];
    const float* ref      = (const float*)d_in[1];
    const int*   e_kernel = (const int*)d_in[2];
    const int*   e_ref    = (const int*)d_in[3];
    const int*   e_query  = (const int*)d_in[4];
    const float* e_weight =
        (n_in >= 7) ? (const float*)d_in[6] : (const float*)d_in[5];

    int E  = in_sizes[2];
    int K0 = in_sizes[0] / (D * D);
    int N  = in_sizes[1] / D;
    int nvec = N * 16;   // float4 count of ref_feat

    cudaMemsetAsync(d_out, 0, (size_t)out_size * sizeof(float), 0);

    hist_kernel<<<256, 256>>>(e_kernel, E);
    scan_kernel<<<1, 32>>>(K0);
    scatfuse_kernel<<<SCAT_BLOCKS + (nvec + 255) / 256, 256>>>(e_kernel, E,
                                                               ref, nvec);

    cudaFuncSetAttribute(mp_mma, cudaFuncAttributeMaxDynamicSharedMemorySize,
                         DYN_SMEM);
    mp_mma<<<GRID, 256, DYN_SMEM>>>(kernelW, e_ref, e_query, e_weight,
                                    (float*)d_out);
}